// round 1
// baseline (speedup 1.0000x reference)
#include <cuda_runtime.h>
#include <math.h>

#define BATCH  65536
#define DIM    512
#define NPROTO 1024

// Scratch (allocation-free rule: __device__ globals)
__device__ float g_z[(size_t)BATCH * DIM];     // 128 MB: z = x@W^T + b
__device__ float g_zsq[BATCH];
__device__ float g_psq[NPROTO];

// ---------------- reductions ----------------
__device__ __forceinline__ float wsum(float v) {
#pragma unroll
    for (int o = 16; o; o >>= 1) v += __shfl_xor_sync(0xffffffffu, v, o);
    return v;
}
__device__ __forceinline__ float wmax(float v) {
#pragma unroll
    for (int o = 16; o; o >>= 1) v = fmaxf(v, __shfl_xor_sync(0xffffffffu, v, o));
    return v;
}

// row-wise sum of squares for 512-wide rows (one block of 128 threads per row)
__global__ __launch_bounds__(128) void row_sumsq_512(const float* __restrict__ X,
                                                     float* __restrict__ out) {
    size_t row = blockIdx.x;
    const float4* p = (const float4*)(X + row * 512);
    float4 v = p[threadIdx.x];
    float s = v.x * v.x + v.y * v.y + v.z * v.z + v.w * v.w;
    s = wsum(s);
    __shared__ float red[4];
    if ((threadIdx.x & 31) == 0) red[threadIdx.x >> 5] = s;
    __syncthreads();
    if (threadIdx.x == 0) out[row] = red[0] + red[1] + red[2] + red[3];
}

// in-place softmax over rows of 1024 (one block of 256 threads per row)
__global__ __launch_bounds__(256) void softmax_1024(float* __restrict__ Wt) {
    size_t row = blockIdx.x;
    float4* p = (float4*)(Wt + row * 1024);
    float4 v = p[threadIdx.x];

    __shared__ float red[8];
    float m = fmaxf(fmaxf(v.x, v.y), fmaxf(v.z, v.w));
    m = wmax(m);
    if ((threadIdx.x & 31) == 0) red[threadIdx.x >> 5] = m;
    __syncthreads();
    if (threadIdx.x < 32) {
        float t = (threadIdx.x < 8) ? red[threadIdx.x] : -INFINITY;
        t = wmax(t);
        if (threadIdx.x == 0) red[0] = t;
    }
    __syncthreads();
    m = red[0];
    __syncthreads();

    v.x = expf(v.x - m); v.y = expf(v.y - m);
    v.z = expf(v.z - m); v.w = expf(v.w - m);
    float s = v.x + v.y + v.z + v.w;
    s = wsum(s);
    __shared__ float red2[8];
    if ((threadIdx.x & 31) == 0) red2[threadIdx.x >> 5] = s;
    __syncthreads();
    if (threadIdx.x < 32) {
        float t = (threadIdx.x < 8) ? red2[threadIdx.x] : 0.0f;
        t = wsum(t);
        if (threadIdx.x == 0) red2[0] = t;
    }
    __syncthreads();
    float inv = 1.0f / red2[0];
    v.x *= inv; v.y *= inv; v.z *= inv; v.w *= inv;
    p[threadIdx.x] = v;
}

// ---------------- GEMMs: 128x128 tile, BK=16, 8x8 per thread, 256 threads ----
// NT: A [M,K] row-major, Bm [N,K] row-major, C = A @ Bm^T (+ epilogue)
// MODE 0: C = A@Bm^T + bias[col]  (encoder fc)
// MODE 1: C = -sqrt(max(zsq[row]+psq[col]-2*(A@Bm^T), 1e-12)) / temp  (scores)
template <int MODE>
__global__ __launch_bounds__(256) void gemm_nt_128(
    const float* __restrict__ A, const float* __restrict__ Bm,
    float* __restrict__ C, const float* __restrict__ bias,
    const float* __restrict__ zsq, const float* __restrict__ psq,
    const float* __restrict__ temp_raw, int K, int ldc) {
    __shared__ float As[16][132];
    __shared__ float Bs[16][132];
    const int tid = threadIdx.x;
    const size_t bm = (size_t)blockIdx.x * 128;
    const size_t bn = (size_t)blockIdx.y * 128;
    const int lrow = (tid >> 4) << 3;   // 0..120
    const int lcol = (tid & 15) << 3;   // 0..120

    float acc[8][8];
#pragma unroll
    for (int i = 0; i < 8; i++)
#pragma unroll
        for (int j = 0; j < 8; j++) acc[i][j] = 0.0f;

    const float* Abase = A + bm * K;
    const float* Bbase = Bm + bn * K;

    for (int k0 = 0; k0 < K; k0 += 16) {
#pragma unroll
        for (int it = 0; it < 2; ++it) {
            int f = tid + it * 256;          // 0..511
            int r = f >> 2;                  // 0..127
            int kc = (f & 3) << 2;           // 0,4,8,12
            float4 va = *(const float4*)(Abase + (size_t)r * K + k0 + kc);
            As[kc + 0][r] = va.x; As[kc + 1][r] = va.y;
            As[kc + 2][r] = va.z; As[kc + 3][r] = va.w;
            float4 vb = *(const float4*)(Bbase + (size_t)r * K + k0 + kc);
            Bs[kc + 0][r] = vb.x; Bs[kc + 1][r] = vb.y;
            Bs[kc + 2][r] = vb.z; Bs[kc + 3][r] = vb.w;
        }
        __syncthreads();
#pragma unroll
        for (int kk = 0; kk < 16; ++kk) {
            float a[8], b[8];
            *(float4*)&a[0] = *(const float4*)&As[kk][lrow];
            *(float4*)&a[4] = *(const float4*)&As[kk][lrow + 4];
            *(float4*)&b[0] = *(const float4*)&Bs[kk][lcol];
            *(float4*)&b[4] = *(const float4*)&Bs[kk][lcol + 4];
#pragma unroll
            for (int i = 0; i < 8; i++)
#pragma unroll
                for (int j = 0; j < 8; j++)
                    acc[i][j] = fmaf(a[i], b[j], acc[i][j]);
        }
        __syncthreads();
    }

    if (MODE == 0) {
        float bv[8];
        *(float4*)&bv[0] = *(const float4*)&bias[bn + lcol];
        *(float4*)&bv[4] = *(const float4*)&bias[bn + lcol + 4];
#pragma unroll
        for (int i = 0; i < 8; i++) {
            float* crow = C + (bm + lrow + i) * ldc + bn + lcol;
            float o[8];
#pragma unroll
            for (int j = 0; j < 8; j++) o[j] = acc[i][j] + bv[j];
            *(float4*)crow = *(float4*)&o[0];
            *(float4*)(crow + 4) = *(float4*)&o[4];
        }
    } else {
        float t = temp_raw[0];
        float temp = 1.0f / (1.0f + expf(-t)) * 0.999f + 0.001f;
        float invt = 1.0f / temp;
        float pv[8];
        *(float4*)&pv[0] = *(const float4*)&psq[bn + lcol];
        *(float4*)&pv[4] = *(const float4*)&psq[bn + lcol + 4];
#pragma unroll
        for (int i = 0; i < 8; i++) {
            float zr = zsq[bm + lrow + i];
            float o[8];
#pragma unroll
            for (int j = 0; j < 8; j++) {
                float d2 = fmaxf(zr + pv[j] - 2.0f * acc[i][j], 1e-12f);
                o[j] = -sqrtf(d2) * invt;
            }
            float* crow = C + (bm + lrow + i) * ldc + bn + lcol;
            *(float4*)crow = *(float4*)&o[0];
            *(float4*)(crow + 4) = *(float4*)&o[4];
        }
    }
}

// NN: A [M,K] row-major, Bm [K,N] row-major, C = A @ Bm
__global__ __launch_bounds__(256) void gemm_nn_128(
    const float* __restrict__ A, const float* __restrict__ Bm,
    float* __restrict__ C, int K, int ldb, int ldc) {
    __shared__ float As[16][132];
    __shared__ float Bs[16][132];
    const int tid = threadIdx.x;
    const size_t bm = (size_t)blockIdx.x * 128;
    const size_t bn = (size_t)blockIdx.y * 128;
    const int lrow = (tid >> 4) << 3;
    const int lcol = (tid & 15) << 3;

    float acc[8][8];
#pragma unroll
    for (int i = 0; i < 8; i++)
#pragma unroll
        for (int j = 0; j < 8; j++) acc[i][j] = 0.0f;

    const float* Abase = A + bm * K;

    for (int k0 = 0; k0 < K; k0 += 16) {
#pragma unroll
        for (int it = 0; it < 2; ++it) {
            int f = tid + it * 256;
            // A tile (transpose into As)
            int r = f >> 2;
            int kc = (f & 3) << 2;
            float4 va = *(const float4*)(Abase + (size_t)r * K + k0 + kc);
            As[kc + 0][r] = va.x; As[kc + 1][r] = va.y;
            As[kc + 2][r] = va.z; As[kc + 3][r] = va.w;
            // B tile (direct): 16 rows x 128 cols
            int kr = f >> 5;            // 0..15
            int nc = (f & 31) << 2;     // 0..124
            float4 vb = *(const float4*)(Bm + (size_t)(k0 + kr) * ldb + bn + nc);
            *(float4*)&Bs[kr][nc] = vb;
        }
        __syncthreads();
#pragma unroll
        for (int kk = 0; kk < 16; ++kk) {
            float a[8], b[8];
            *(float4*)&a[0] = *(const float4*)&As[kk][lrow];
            *(float4*)&a[4] = *(const float4*)&As[kk][lrow + 4];
            *(float4*)&b[0] = *(const float4*)&Bs[kk][lcol];
            *(float4*)&b[4] = *(const float4*)&Bs[kk][lcol + 4];
#pragma unroll
            for (int i = 0; i < 8; i++)
#pragma unroll
                for (int j = 0; j < 8; j++)
                    acc[i][j] = fmaf(a[i], b[j], acc[i][j]);
        }
        __syncthreads();
    }

#pragma unroll
    for (int i = 0; i < 8; i++) {
        float* crow = C + (bm + lrow + i) * ldc + bn + lcol;
        *(float4*)crow = *(float4*)&acc[i][0];
        *(float4*)(crow + 4) = *(float4*)&acc[i][4];
    }
}

extern "C" void kernel_launch(void* const* d_in, const int* in_sizes, int n_in,
                              void* d_out, int out_size) {
    const float* x  = (const float*)d_in[0];   // [B, D]
    const float* W  = (const float*)d_in[1];   // [D, D]
    const float* b  = (const float*)d_in[2];   // [D]
    const float* P  = (const float*)d_in[3];   // [N, D]
    const float* tr = (const float*)d_in[4];   // [1]

    float* blended = (float*)d_out;                          // [B, D]
    float* weights = (float*)d_out + (size_t)BATCH * DIM;    // [B, N]

    float *z, *zsq, *psq;
    cudaGetSymbolAddress((void**)&z,   g_z);
    cudaGetSymbolAddress((void**)&zsq, g_zsq);
    cudaGetSymbolAddress((void**)&psq, g_psq);

    // 1) prototype squared norms
    row_sumsq_512<<<NPROTO, 128>>>(P, psq);

    // 2) z = x @ W^T + b
    gemm_nt_128<0><<<dim3(BATCH / 128, DIM / 128), 256>>>(
        x, W, z, b, nullptr, nullptr, nullptr, DIM, DIM);

    // 3) z squared norms
    row_sumsq_512<<<BATCH, 128>>>(z, zsq);

    // 4) scores = -sqrt(max(zsq + psq - 2 z@P^T, 1e-12)) / temp
    gemm_nt_128<1><<<dim3(BATCH / 128, NPROTO / 128), 256>>>(
        z, P, weights, nullptr, zsq, psq, tr, DIM, NPROTO);

    // 5) softmax rows -> weights
    softmax_1024<<<BATCH, 256>>>(weights);

    // 6) blended = weights @ P
    gemm_nn_128<<<dim3(BATCH / 128, DIM / 128), 256>>>(
        weights, P, blended, NPROTO, DIM, DIM);
}